// round 3
// baseline (speedup 1.0000x reference)
#include <cuda_runtime.h>

#define N_UTT 16384
#define DIM   256
#define WHALF 64
#define WIN   128   // 2*WHALF
#define G     8     // rows per CTA in fused kernel

// Scratch: [0]=Q=x@W_att, [1]=x@W_pred, [2]=x@W_suc, [3]=x@W_same, [4]=x@W_diff
__device__ float g_scratch[5ULL * N_UTT * DIM];

struct WPtrs { const float* w[5]; };

// ---------------------------------------------------------------------------
// SGEMM: g_scratch[widx] = X[16384,256] @ W[widx][256,256]
// BM=BN=128, BK=8, 256 threads, 8x8 microtile per thread.
// grid = (128 row tiles, 10 col tiles); col tile -> (widx = by/2, col0 = (by&1)*128)
// ---------------------------------------------------------------------------
__global__ __launch_bounds__(256) void gemm_kernel(const float* __restrict__ X, WPtrs wp) {
    const int bx   = blockIdx.x;
    const int by   = blockIdx.y;
    const int widx = by >> 1;
    const int col0 = (by & 1) * 128;
    const float* __restrict__ B = wp.w[widx];
    float* __restrict__ Cout = g_scratch + (size_t)widx * N_UTT * DIM;

    __shared__ float As[8 * 128];   // [k][m]
    __shared__ float Bs[8 * 128];   // [k][n]

    const int tid  = threadIdx.x;
    const int tx   = tid & 15;      // 16 cols of threads
    const int ty   = tid >> 4;      // 16 rows of threads
    const int row0 = bx * 128;

    float acc[8][8];
#pragma unroll
    for (int i = 0; i < 8; i++)
#pragma unroll
        for (int j = 0; j < 8; j++) acc[i][j] = 0.f;

    const int arow = tid >> 1;          // 0..127
    const int acol = (tid & 1) * 4;     // 0 or 4
    const int brow = tid >> 5;          // 0..7
    const int bcol = (tid & 31) * 4;    // 0..124

    for (int k0 = 0; k0 < 256; k0 += 8) {
        float4 av = *reinterpret_cast<const float4*>(&X[(size_t)(row0 + arow) * DIM + k0 + acol]);
        float4 bv = *reinterpret_cast<const float4*>(&B[(size_t)(k0 + brow) * DIM + col0 + bcol]);
        __syncthreads();
        As[(acol + 0) * 128 + arow] = av.x;
        As[(acol + 1) * 128 + arow] = av.y;
        As[(acol + 2) * 128 + arow] = av.z;
        As[(acol + 3) * 128 + arow] = av.w;
        *reinterpret_cast<float4*>(&Bs[brow * 128 + bcol]) = bv;
        __syncthreads();
#pragma unroll
        for (int kk = 0; kk < 8; kk++) {
            float4 a0 = *reinterpret_cast<const float4*>(&As[kk * 128 + ty * 8]);
            float4 a1 = *reinterpret_cast<const float4*>(&As[kk * 128 + ty * 8 + 4]);
            float4 b0 = *reinterpret_cast<const float4*>(&Bs[kk * 128 + tx * 8]);
            float4 b1 = *reinterpret_cast<const float4*>(&Bs[kk * 128 + tx * 8 + 4]);
            float ar[8] = {a0.x, a0.y, a0.z, a0.w, a1.x, a1.y, a1.z, a1.w};
            float br[8] = {b0.x, b0.y, b0.z, b0.w, b1.x, b1.y, b1.z, b1.w};
#pragma unroll
            for (int i = 0; i < 8; i++)
#pragma unroll
                for (int j = 0; j < 8; j++)
                    acc[i][j] = fmaf(ar[i], br[j], acc[i][j]);
        }
    }

#pragma unroll
    for (int rr = 0; rr < 8; rr++) {
        size_t base = (size_t)(row0 + ty * 8 + rr) * DIM + col0 + tx * 8;
        *reinterpret_cast<float4*>(&Cout[base]) =
            make_float4(acc[rr][0], acc[rr][1], acc[rr][2], acc[rr][3]);
        *reinterpret_cast<float4*>(&Cout[base + 4]) =
            make_float4(acc[rr][4], acc[rr][5], acc[rr][6], acc[rr][7]);
    }
}

// ---------------------------------------------------------------------------
// Fused: band attention softmax + relation-masked aggregation + log_softmax.
// One CTA (256 threads) handles G=8 consecutive rows i0..i0+7.
// ---------------------------------------------------------------------------
__device__ __forceinline__ float warpMax(float v) {
#pragma unroll
    for (int o = 16; o > 0; o >>= 1) v = fmaxf(v, __shfl_xor_sync(0xffffffffu, v, o));
    return v;
}
__device__ __forceinline__ float warpSum(float v) {
#pragma unroll
    for (int o = 16; o > 0; o >>= 1) v += __shfl_xor_sync(0xffffffffu, v, o);
    return v;
}

__global__ __launch_bounds__(256) void fused_kernel(const float* __restrict__ x,
                                                    const int* __restrict__ spk,
                                                    float* __restrict__ out) {
    __shared__ float sq[G][DIM];      // q rows (x @ W_att)
    __shared__ float sattn[G][WIN];   // normalized attention (0 for invalid j)
    __shared__ float sred[8];

    const int i0   = blockIdx.x * G;
    const int tid  = threadIdx.x;
    const int wi   = tid >> 5;
    const int lane = tid & 31;

    const float* __restrict__ Q  = g_scratch;
    const float* __restrict__ Sp = g_scratch + 1ULL * N_UTT * DIM;
    const float* __restrict__ Ss = g_scratch + 2ULL * N_UTT * DIM;
    const float* __restrict__ Sm = g_scratch + 3ULL * N_UTT * DIM;
    const float* __restrict__ Sd = g_scratch + 4ULL * N_UTT * DIM;

    // ---- load q rows for the 8 utterances ----
#pragma unroll
    for (int li = 0; li < G; li++)
        sq[li][tid] = Q[(size_t)(i0 + li) * DIM + tid];
    __syncthreads();

    // ---- attention: warp wi owns row i0+wi ----
    {
        const int i = i0 + wi;
        for (int w = 0; w < WIN; w++) {
            const int j = i + w - WHALF;
            float r = 0.f;
            if (j >= 0 && j < N_UTT) {
                const float* __restrict__ xr = &x[(size_t)j * DIM];
#pragma unroll
                for (int m = 0; m < 8; m++) {
                    const int d = lane + 32 * m;
                    r = fmaf(xr[d], sq[wi][d], r);
                }
            }
            r = warpSum(r);
            if (lane == 0) sattn[wi][w] = r;   // raw logit (0 for invalid slot)
        }
        __syncwarp();

        // softmax over all 128 slots (invalid slots included in denominator)
        float v[4];
#pragma unroll
        for (int s = 0; s < 4; s++) v[s] = sattn[wi][lane + 32 * s];
        float m = fmaxf(fmaxf(v[0], v[1]), fmaxf(v[2], v[3]));
        m = warpMax(m);
        float e[4], lsum = 0.f;
#pragma unroll
        for (int s = 0; s < 4; s++) { e[s] = __expf(v[s] - m); lsum += e[s]; }
        lsum = warpSum(lsum);
        const float inv = 1.f / lsum;
#pragma unroll
        for (int s = 0; s < 4; s++) {
            const int w = lane + 32 * s;
            const int j = i + w - WHALF;
            sattn[wi][w] = (j >= 0 && j < N_UTT) ? e[s] * inv : 0.f;
        }
    }
    __syncthreads();

    // ---- aggregation: thread owns feature d, loop over union window of j ----
    const int d = tid;
    float acc[G];
    int spk_i[G];
#pragma unroll
    for (int li = 0; li < G; li++) { acc[li] = 0.f; spk_i[li] = spk[i0 + li]; }

    for (int jj = 0; jj < WIN + G - 1; jj++) {   // 135 rows: j in [i0-64, i0+70]
        const int j = i0 - WHALF + jj;
        if (j < 0 || j >= N_UTT) continue;
        const size_t off = (size_t)j * DIM + d;
        const float vp = Sp[off];
        const float vs = Ss[off];
        const float vm = Sm[off];
        const float vd = Sd[off];
        const int sj = spk[j];
#pragma unroll
        for (int li = 0; li < G; li++) {
            const int w = jj - li;                 // offset slot for row i0+li
            if (w >= 0 && w < WIN) {
                const float c   = sattn[li][w];    // 0 if edge invalid
                const float dir = (w >= WHALF) ? vp : vs;
                const float sv  = (sj == spk_i[li]) ? vm : vd;
                acc[li] = fmaf(c, dir + sv, acc[li]);
            }
        }
    }

    // ---- log_softmax over D for each of the 8 rows ----
#pragma unroll
    for (int li = 0; li < G; li++) {
        const float v = acc[li];
        float m = warpMax(v);
        if (lane == 0) sred[wi] = m;
        __syncthreads();
        float bm = sred[0];
#pragma unroll
        for (int k = 1; k < 8; k++) bm = fmaxf(bm, sred[k]);
        __syncthreads();
        float e = __expf(v - bm);
        float s = warpSum(e);
        if (lane == 0) sred[wi] = s;
        __syncthreads();
        float bs = sred[0];
#pragma unroll
        for (int k = 1; k < 8; k++) bs += sred[k];
        __syncthreads();
        out[(size_t)(i0 + li) * DIM + d] = (v - bm) - logf(bs);
    }
}

// ---------------------------------------------------------------------------
extern "C" void kernel_launch(void* const* d_in, const int* in_sizes, int n_in,
                              void* d_out, int out_size) {
    const float* x   = (const float*)d_in[0];
    const int*   spk = (const int*)d_in[1];
    WPtrs wp;
    wp.w[0] = (const float*)d_in[2];  // W_att
    wp.w[1] = (const float*)d_in[3];  // W_pred
    wp.w[2] = (const float*)d_in[4];  // W_suc
    wp.w[3] = (const float*)d_in[5];  // W_same
    wp.w[4] = (const float*)d_in[6];  // W_diff
    float* out = (float*)d_out;

    dim3 ggrid(N_UTT / 128, 10);
    gemm_kernel<<<ggrid, 256>>>(x, wp);
    fused_kernel<<<N_UTT / G, 256>>>(x, spk, out);
}

// round 4
// speedup vs baseline: 1.3495x; 1.3495x over previous
#include <cuda_runtime.h>

#define N_UTT 16384
#define DIM   256
#define WHALF 64
#define WIN   128           // 2*WHALF
#define G     8             // rows per CTA in fused kernel
#define NW    135           // WIN + G - 1  (union window rows)
#define DCH   32            // d-chunk width for attention x staging
#define XWPITCH 36          // DCH + 4 pad (stride ≡ 4 mod 32 -> conflict-free LDS.128)

// Scratch: [0]=Q=x@W_att, [1]=x@W_pred, [2]=x@W_suc, [3]=x@W_same, [4]=x@W_diff
__device__ float g_scratch[5ULL * N_UTT * DIM];

struct WPtrs { const float* w[5]; };

// ---------------------------------------------------------------------------
// SGEMM (double-buffered): g_scratch[widx] = X[16384,256] @ W[widx][256,256]
// BM=BN=128, BK=8, 256 threads, 8x8 microtile.
// ---------------------------------------------------------------------------
__global__ __launch_bounds__(256) void gemm_kernel(const float* __restrict__ X, WPtrs wp) {
    const int bx   = blockIdx.x;
    const int by   = blockIdx.y;
    const int widx = by >> 1;
    const int col0 = (by & 1) * 128;
    const float* __restrict__ B = wp.w[widx];
    float* __restrict__ Cout = g_scratch + (size_t)widx * N_UTT * DIM;

    __shared__ float As[2][8 * 128];   // [k][m]
    __shared__ float Bs[2][8 * 128];   // [k][n]

    const int tid  = threadIdx.x;
    const int tx   = tid & 15;
    const int ty   = tid >> 4;
    const int row0 = bx * 128;

    float acc[8][8];
#pragma unroll
    for (int i = 0; i < 8; i++)
#pragma unroll
        for (int j = 0; j < 8; j++) acc[i][j] = 0.f;

    const int arow = tid >> 1;
    const int acol = (tid & 1) * 4;
    const int brow = tid >> 5;
    const int bcol = (tid & 31) * 4;

    // prologue: chunk 0
    {
        float4 av = *reinterpret_cast<const float4*>(&X[(size_t)(row0 + arow) * DIM + acol]);
        float4 bv = *reinterpret_cast<const float4*>(&B[(size_t)brow * DIM + col0 + bcol]);
        As[0][(acol + 0) * 128 + arow] = av.x;
        As[0][(acol + 1) * 128 + arow] = av.y;
        As[0][(acol + 2) * 128 + arow] = av.z;
        As[0][(acol + 3) * 128 + arow] = av.w;
        *reinterpret_cast<float4*>(&Bs[0][brow * 128 + bcol]) = bv;
    }
    __syncthreads();

    int cur = 0;
    for (int k0 = 0; k0 < 256; k0 += 8) {
        float4 av2, bv2;
        const bool has_next = (k0 + 8 < 256);
        if (has_next) {
            av2 = *reinterpret_cast<const float4*>(&X[(size_t)(row0 + arow) * DIM + k0 + 8 + acol]);
            bv2 = *reinterpret_cast<const float4*>(&B[(size_t)(k0 + 8 + brow) * DIM + col0 + bcol]);
        }
#pragma unroll
        for (int kk = 0; kk < 8; kk++) {
            float4 a0 = *reinterpret_cast<const float4*>(&As[cur][kk * 128 + ty * 8]);
            float4 a1 = *reinterpret_cast<const float4*>(&As[cur][kk * 128 + ty * 8 + 4]);
            float4 b0 = *reinterpret_cast<const float4*>(&Bs[cur][kk * 128 + tx * 8]);
            float4 b1 = *reinterpret_cast<const float4*>(&Bs[cur][kk * 128 + tx * 8 + 4]);
            float ar[8] = {a0.x, a0.y, a0.z, a0.w, a1.x, a1.y, a1.z, a1.w};
            float br[8] = {b0.x, b0.y, b0.z, b0.w, b1.x, b1.y, b1.z, b1.w};
#pragma unroll
            for (int i = 0; i < 8; i++)
#pragma unroll
                for (int j = 0; j < 8; j++)
                    acc[i][j] = fmaf(ar[i], br[j], acc[i][j]);
        }
        if (has_next) {
            const int nxt = cur ^ 1;
            As[nxt][(acol + 0) * 128 + arow] = av2.x;
            As[nxt][(acol + 1) * 128 + arow] = av2.y;
            As[nxt][(acol + 2) * 128 + arow] = av2.z;
            As[nxt][(acol + 3) * 128 + arow] = av2.w;
            *reinterpret_cast<float4*>(&Bs[nxt][brow * 128 + bcol]) = bv2;
            __syncthreads();
            cur = nxt;
        }
    }

#pragma unroll
    for (int rr = 0; rr < 8; rr++) {
        size_t base = (size_t)(row0 + ty * 8 + rr) * DIM + col0 + tx * 8;
        *reinterpret_cast<float4*>(&Cout[base]) =
            make_float4(acc[rr][0], acc[rr][1], acc[rr][2], acc[rr][3]);
        *reinterpret_cast<float4*>(&Cout[base + 4]) =
            make_float4(acc[rr][4], acc[rr][5], acc[rr][6], acc[rr][7]);
    }
}

// ---------------------------------------------------------------------------
// Fused: band attention softmax + relation-masked aggregation + log_softmax.
// One CTA (256 threads) handles G=8 consecutive rows.
// ---------------------------------------------------------------------------
__device__ __forceinline__ float warpMax(float v) {
#pragma unroll
    for (int o = 16; o > 0; o >>= 1) v = fmaxf(v, __shfl_xor_sync(0xffffffffu, v, o));
    return v;
}
__device__ __forceinline__ float warpSum(float v) {
#pragma unroll
    for (int o = 16; o > 0; o >>= 1) v += __shfl_xor_sync(0xffffffffu, v, o);
    return v;
}

__global__ __launch_bounds__(256) void fused_kernel(const float* __restrict__ x,
                                                    const int* __restrict__ spk,
                                                    float* __restrict__ out) {
    __shared__ float  sq[G][DIM];          // q rows (x @ W_att)           8 KB
    __shared__ float  xw[NW * XWPITCH];    // staged x window d-chunk     19.4 KB
    __shared__ float  sattn[G][WIN];       // normalized attention         4 KB
    __shared__ float2 cs2[G][NW];          // (c, ±c/2) coefficients       8.6 KB
    __shared__ int    spkw[NW];            // speaker ids of window
    __shared__ float  sred[8];

    const int i0   = blockIdx.x * G;
    const int tid  = threadIdx.x;
    const int wi   = tid >> 5;
    const int lane = tid & 31;

    const float* __restrict__ Q  = g_scratch;
    const float* __restrict__ Sp = g_scratch + 1ULL * N_UTT * DIM;
    const float* __restrict__ Ss = g_scratch + 2ULL * N_UTT * DIM;
    const float* __restrict__ Sm = g_scratch + 3ULL * N_UTT * DIM;
    const float* __restrict__ Sd = g_scratch + 4ULL * N_UTT * DIM;

    // ---- load q rows + speaker window ----
#pragma unroll
    for (int li = 0; li < G; li++)
        sq[li][tid] = Q[(size_t)(i0 + li) * DIM + tid];
    if (tid < NW) {
        int j = i0 + tid - WHALF;
        j = min(max(j, 0), N_UTT - 1);
        spkw[tid] = spk[j];
    }
    __syncthreads();

    // ---- attention logits: lane owns w = lane + 32*s, jj = wi + w ----
    float r0 = 0.f, r1 = 0.f, r2 = 0.f, r3 = 0.f;
    for (int c0 = 0; c0 < DIM; c0 += DCH) {
        // stage x window chunk (zero-filled out of range -> logits match padding)
        for (int t = tid; t < NW * 8; t += 256) {
            const int row = t >> 3, f = t & 7;
            const int j = i0 + row - WHALF;
            float4 v = make_float4(0.f, 0.f, 0.f, 0.f);
            if (j >= 0 && j < N_UTT)
                v = *reinterpret_cast<const float4*>(&x[(size_t)j * DIM + c0 + 4 * f]);
            *reinterpret_cast<float4*>(&xw[row * XWPITCH + 4 * f]) = v;
        }
        __syncthreads();
#pragma unroll
        for (int d4 = 0; d4 < DCH / 4; d4++) {
            const float4 q4 = *reinterpret_cast<const float4*>(&sq[wi][c0 + 4 * d4]);
            const float* xb = &xw[4 * d4];
            const float4 a0 = *reinterpret_cast<const float4*>(&xb[(wi + lane) * XWPITCH]);
            const float4 a1 = *reinterpret_cast<const float4*>(&xb[(wi + lane + 32) * XWPITCH]);
            const float4 a2 = *reinterpret_cast<const float4*>(&xb[(wi + lane + 64) * XWPITCH]);
            const float4 a3 = *reinterpret_cast<const float4*>(&xb[(wi + lane + 96) * XWPITCH]);
            r0 = fmaf(q4.x, a0.x, fmaf(q4.y, a0.y, fmaf(q4.z, a0.z, fmaf(q4.w, a0.w, r0))));
            r1 = fmaf(q4.x, a1.x, fmaf(q4.y, a1.y, fmaf(q4.z, a1.z, fmaf(q4.w, a1.w, r1))));
            r2 = fmaf(q4.x, a2.x, fmaf(q4.y, a2.y, fmaf(q4.z, a2.z, fmaf(q4.w, a2.w, r2))));
            r3 = fmaf(q4.x, a3.x, fmaf(q4.y, a3.y, fmaf(q4.z, a3.z, fmaf(q4.w, a3.w, r3))));
        }
        __syncthreads();
    }

    // ---- softmax over the 128 slots (invalid slots carry raw=0, matching ref) ----
    {
        const int i = i0 + wi;
        float m = warpMax(fmaxf(fmaxf(r0, r1), fmaxf(r2, r3)));
        const float e0 = __expf(r0 - m), e1 = __expf(r1 - m),
                    e2 = __expf(r2 - m), e3 = __expf(r3 - m);
        const float inv = 1.f / warpSum(e0 + e1 + e2 + e3);
        int j;
        j = i + lane - WHALF;       sattn[wi][lane]      = (j >= 0 && j < N_UTT) ? e0 * inv : 0.f;
        j = i + lane - WHALF + 32;  sattn[wi][lane + 32] = (j >= 0 && j < N_UTT) ? e1 * inv : 0.f;
        j = i + lane - WHALF + 64;  sattn[wi][lane + 64] = (j >= 0 && j < N_UTT) ? e2 * inv : 0.f;
        j = i + lane - WHALF + 96;  sattn[wi][lane + 96] = (j >= 0 && j < N_UTT) ? e3 * inv : 0.f;
    }
    __syncthreads();

    // ---- build fused coefficients: cs2[li][jj] = (c, +c/2 if same spk else -c/2) ----
    for (int t = tid; t < G * NW; t += 256) {
        const int li = t / NW, jj = t - li * NW;
        const int w = jj - li;
        float c = 0.f;
        if (w >= 0 && w < WIN) c = sattn[li][w];   // already 0 for invalid j
        const float s = (spkw[jj] == spkw[WHALF + li]) ? 0.5f * c : -0.5f * c;
        cs2[li][jj] = make_float2(c, s);
    }
    __syncthreads();

    // ---- aggregation: thread owns feature d, stream union window ----
    const int d = tid;
    float acc[G];
    int myspk[G];
#pragma unroll
    for (int li = 0; li < G; li++) { acc[li] = 0.f; myspk[li] = spkw[WHALF + li]; }

    const int jlo = (i0 < WHALF) ? (WHALF - i0) : 0;
    const int jhi = min(NW, N_UTT - i0 + WHALF);

    // region 1: all suc (w < 64 for every li)
    for (int jj = jlo; jj < WHALF; jj++) {
        const size_t off = (size_t)(i0 + jj - WHALF) * DIM + d;
        const float vs = Ss[off], vm = Sm[off], vd = Sd[off];
        const float t1 = vs + 0.5f * (vm + vd);
        const float t2 = vm - vd;
#pragma unroll
        for (int li = 0; li < G; li++) {
            const float2 cs = cs2[li][jj];
            acc[li] = fmaf(cs.x, t1, fmaf(cs.y, t2, acc[li]));
        }
    }
    // region 2: mixed direction, 7 iterations (j always valid here)
#pragma unroll
    for (int jj = WHALF; jj < WHALF + G - 1; jj++) {
        const size_t off = (size_t)(i0 + jj - WHALF) * DIM + d;
        const float vp = Sp[off], vs = Ss[off], vm = Sm[off], vd = Sd[off];
        const int sj = spkw[jj];
#pragma unroll
        for (int li = 0; li < G; li++) {
            const int w = jj - li;                 // 57..70, always in band
            const float c   = sattn[li][w];
            const float dir = (w >= WHALF) ? vp : vs;
            const float sv  = (sj == myspk[li]) ? vm : vd;
            acc[li] = fmaf(c, dir + sv, acc[li]);
        }
    }
    // region 3: all pred (w >= 64 for every li)
    for (int jj = WHALF + G - 1; jj < jhi; jj++) {
        const size_t off = (size_t)(i0 + jj - WHALF) * DIM + d;
        const float vp = Sp[off], vm = Sm[off], vd = Sd[off];
        const float t1 = vp + 0.5f * (vm + vd);
        const float t2 = vm - vd;
#pragma unroll
        for (int li = 0; li < G; li++) {
            const float2 cs = cs2[li][jj];
            acc[li] = fmaf(cs.x, t1, fmaf(cs.y, t2, acc[li]));
        }
    }

    // ---- log_softmax over D for each of the 8 rows ----
#pragma unroll
    for (int li = 0; li < G; li++) {
        const float v = acc[li];
        float m = warpMax(v);
        if (lane == 0) sred[wi] = m;
        __syncthreads();
        float bm = sred[0];
#pragma unroll
        for (int k = 1; k < 8; k++) bm = fmaxf(bm, sred[k]);
        __syncthreads();
        float e = __expf(v - bm);
        float s = warpSum(e);
        if (lane == 0) sred[wi] = s;
        __syncthreads();
        float bs = sred[0];
#pragma unroll
        for (int k = 1; k < 8; k++) bs += sred[k];
        __syncthreads();
        out[(size_t)(i0 + li) * DIM + d] = (v - bm) - logf(bs);
    }
}

// ---------------------------------------------------------------------------
extern "C" void kernel_launch(void* const* d_in, const int* in_sizes, int n_in,
                              void* d_out, int out_size) {
    const float* x   = (const float*)d_in[0];
    const int*   spk = (const int*)d_in[1];
    WPtrs wp;
    wp.w[0] = (const float*)d_in[2];  // W_att
    wp.w[1] = (const float*)d_in[3];  // W_pred
    wp.w[2] = (const float*)d_in[4];  // W_suc
    wp.w[3] = (const float*)d_in[5];  // W_same
    wp.w[4] = (const float*)d_in[6];  // W_diff
    float* out = (float*)d_out;

    dim3 ggrid(N_UTT / 128, 10);
    gemm_kernel<<<ggrid, 256>>>(x, wp);
    fused_kernel<<<N_UTT / G, 256>>>(x, spk, out);
}

// round 8
// speedup vs baseline: 1.7356x; 1.2861x over previous
#include <cuda_runtime.h>

#define N_UTT 16384
#define DIM   256
#define WHALF 64
#define WIN   128           // 2*WHALF
#define G     8             // rows per CTA in fused kernel
#define NW    135           // WIN + G - 1  (union window rows)
#define DCH   32            // d-chunk width for attention x staging
#define XWPITCH 36          // DCH + 4 pad (conflict-free LDS.128)

// Scratch: [0]=Q=x@W_att, [1]=T1p=x@Wc1, [2]=T1s=x@Wc2, [3]=T2=x@Wc3
__device__ float g_scratch[4ULL * N_UTT * DIM];
// Combined weights: Wc1 = Wp + 0.5(Wm+Wd), Wc2 = Ws + 0.5(Wm+Wd), Wc3 = Wm - Wd
__device__ float g_wc[3ULL * DIM * DIM];

struct WPtrs { const float* w[4]; };

// ---------------------------------------------------------------------------
// Weight combine: 3 x 256x256 elementwise
// ---------------------------------------------------------------------------
__global__ void combine_kernel(const float* __restrict__ Wp, const float* __restrict__ Ws,
                               const float* __restrict__ Wm, const float* __restrict__ Wd) {
    const int i = (blockIdx.x * blockDim.x + threadIdx.x) * 4;
    float4 p = *reinterpret_cast<const float4*>(&Wp[i]);
    float4 s = *reinterpret_cast<const float4*>(&Ws[i]);
    float4 m = *reinterpret_cast<const float4*>(&Wm[i]);
    float4 d = *reinterpret_cast<const float4*>(&Wd[i]);
    float4 avg = make_float4(0.5f * (m.x + d.x), 0.5f * (m.y + d.y),
                             0.5f * (m.z + d.z), 0.5f * (m.w + d.w));
    *reinterpret_cast<float4*>(&g_wc[i]) =
        make_float4(p.x + avg.x, p.y + avg.y, p.z + avg.z, p.w + avg.w);
    *reinterpret_cast<float4*>(&g_wc[DIM * DIM + i]) =
        make_float4(s.x + avg.x, s.y + avg.y, s.z + avg.z, s.w + avg.w);
    *reinterpret_cast<float4*>(&g_wc[2 * DIM * DIM + i]) =
        make_float4(m.x - d.x, m.y - d.y, m.z - d.z, m.w - d.w);
}

// ---------------------------------------------------------------------------
// SGEMM (double-buffered): g_scratch[widx] = X[16384,256] @ W[widx][256,256]
// BM=BN=128, BK=8, 256 threads, 8x8 microtile.  grid=(128, 8)
// ---------------------------------------------------------------------------
__global__ __launch_bounds__(256) void gemm_kernel(const float* __restrict__ X, WPtrs wp) {
    const int bx   = blockIdx.x;
    const int by   = blockIdx.y;
    const int widx = by >> 1;
    const int col0 = (by & 1) * 128;
    const float* __restrict__ B = wp.w[widx];
    float* __restrict__ Cout = g_scratch + (size_t)widx * N_UTT * DIM;

    __shared__ float As[2][8 * 128];   // [k][m]
    __shared__ float Bs[2][8 * 128];   // [k][n]

    const int tid  = threadIdx.x;
    const int tx   = tid & 15;
    const int ty   = tid >> 4;
    const int row0 = bx * 128;

    float acc[8][8];
#pragma unroll
    for (int i = 0; i < 8; i++)
#pragma unroll
        for (int j = 0; j < 8; j++) acc[i][j] = 0.f;

    const int arow = tid >> 1;
    const int acol = (tid & 1) * 4;
    const int brow = tid >> 5;
    const int bcol = (tid & 31) * 4;

    {
        float4 av = *reinterpret_cast<const float4*>(&X[(size_t)(row0 + arow) * DIM + acol]);
        float4 bv = *reinterpret_cast<const float4*>(&B[(size_t)brow * DIM + col0 + bcol]);
        As[0][(acol + 0) * 128 + arow] = av.x;
        As[0][(acol + 1) * 128 + arow] = av.y;
        As[0][(acol + 2) * 128 + arow] = av.z;
        As[0][(acol + 3) * 128 + arow] = av.w;
        *reinterpret_cast<float4*>(&Bs[0][brow * 128 + bcol]) = bv;
    }
    __syncthreads();

    int cur = 0;
    for (int k0 = 0; k0 < 256; k0 += 8) {
        float4 av2, bv2;
        const bool has_next = (k0 + 8 < 256);
        if (has_next) {
            av2 = *reinterpret_cast<const float4*>(&X[(size_t)(row0 + arow) * DIM + k0 + 8 + acol]);
            bv2 = *reinterpret_cast<const float4*>(&B[(size_t)(k0 + 8 + brow) * DIM + col0 + bcol]);
        }
#pragma unroll
        for (int kk = 0; kk < 8; kk++) {
            float4 a0 = *reinterpret_cast<const float4*>(&As[cur][kk * 128 + ty * 8]);
            float4 a1 = *reinterpret_cast<const float4*>(&As[cur][kk * 128 + ty * 8 + 4]);
            float4 b0 = *reinterpret_cast<const float4*>(&Bs[cur][kk * 128 + tx * 8]);
            float4 b1 = *reinterpret_cast<const float4*>(&Bs[cur][kk * 128 + tx * 8 + 4]);
            float ar[8] = {a0.x, a0.y, a0.z, a0.w, a1.x, a1.y, a1.z, a1.w};
            float br[8] = {b0.x, b0.y, b0.z, b0.w, b1.x, b1.y, b1.z, b1.w};
#pragma unroll
            for (int i = 0; i < 8; i++)
#pragma unroll
                for (int j = 0; j < 8; j++)
                    acc[i][j] = fmaf(ar[i], br[j], acc[i][j]);
        }
        if (has_next) {
            const int nxt = cur ^ 1;
            As[nxt][(acol + 0) * 128 + arow] = av2.x;
            As[nxt][(acol + 1) * 128 + arow] = av2.y;
            As[nxt][(acol + 2) * 128 + arow] = av2.z;
            As[nxt][(acol + 3) * 128 + arow] = av2.w;
            *reinterpret_cast<float4*>(&Bs[nxt][brow * 128 + bcol]) = bv2;
            __syncthreads();
            cur = nxt;
        }
    }

#pragma unroll
    for (int rr = 0; rr < 8; rr++) {
        size_t base = (size_t)(row0 + ty * 8 + rr) * DIM + col0 + tx * 8;
        *reinterpret_cast<float4*>(&Cout[base]) =
            make_float4(acc[rr][0], acc[rr][1], acc[rr][2], acc[rr][3]);
        *reinterpret_cast<float4*>(&Cout[base + 4]) =
            make_float4(acc[rr][4], acc[rr][5], acc[rr][6], acc[rr][7]);
    }
}

// ---------------------------------------------------------------------------
// Fused: band attention softmax + relation aggregation + log_softmax.
// ---------------------------------------------------------------------------
__device__ __forceinline__ float warpMax(float v) {
#pragma unroll
    for (int o = 16; o > 0; o >>= 1) v = fmaxf(v, __shfl_xor_sync(0xffffffffu, v, o));
    return v;
}
__device__ __forceinline__ float warpSum(float v) {
#pragma unroll
    for (int o = 16; o > 0; o >>= 1) v += __shfl_xor_sync(0xffffffffu, v, o);
    return v;
}

__global__ __launch_bounds__(256) void fused_kernel(const float* __restrict__ x,
                                                    const int* __restrict__ spk,
                                                    float* __restrict__ out) {
    __shared__ float  sq[G][DIM];                  // q rows; reused as acc transpose (8 KB)
    __shared__ float4 sbuf4[(NW * XWPITCH + 3) / 4]; // 19.4 KB: xw, then coef tables
    __shared__ float  sattn[G][WIN];               // 4 KB
    __shared__ int    spkw[NW];
    __shared__ float  slse[G];

    float* const xw   = reinterpret_cast<float*>(sbuf4);
    float* const csAp = reinterpret_cast<float*>(sbuf4);              // [NW][G]
    float* const csAs = reinterpret_cast<float*>(sbuf4) + NW * G;     // [NW][G]
    float* const csB  = reinterpret_cast<float*>(sbuf4) + 2 * NW * G; // [NW][G]

    const int i0   = blockIdx.x * G;
    const int tid  = threadIdx.x;
    const int wi   = tid >> 5;
    const int lane = tid & 31;

    const float* __restrict__ Q   = g_scratch;
    const float* __restrict__ T1p = g_scratch + 1ULL * N_UTT * DIM;
    const float* __restrict__ T1s = g_scratch + 2ULL * N_UTT * DIM;
    const float* __restrict__ T2  = g_scratch + 3ULL * N_UTT * DIM;

    // ---- load q rows + speaker window ----
#pragma unroll
    for (int li = 0; li < G; li++)
        sq[li][tid] = Q[(size_t)(i0 + li) * DIM + tid];
    if (tid < NW) {
        int j = i0 + tid - WHALF;
        j = min(max(j, 0), N_UTT - 1);
        spkw[tid] = spk[j];
    }
    __syncthreads();

    // ---- attention logits: lane owns w = lane + 32*s, jj = wi + w ----
    float r0 = 0.f, r1 = 0.f, r2 = 0.f, r3 = 0.f;
    for (int c0 = 0; c0 < DIM; c0 += DCH) {
        for (int t = tid; t < NW * 8; t += 256) {
            const int row = t >> 3, f = t & 7;
            const int j = i0 + row - WHALF;
            float4 v = make_float4(0.f, 0.f, 0.f, 0.f);
            if (j >= 0 && j < N_UTT)
                v = *reinterpret_cast<const float4*>(&x[(size_t)j * DIM + c0 + 4 * f]);
            *reinterpret_cast<float4*>(&xw[row * XWPITCH + 4 * f]) = v;
        }
        __syncthreads();
#pragma unroll
        for (int d4 = 0; d4 < DCH / 4; d4++) {
            const float4 q4 = *reinterpret_cast<const float4*>(&sq[wi][c0 + 4 * d4]);
            const float* xb = &xw[4 * d4];
            const float4 a0 = *reinterpret_cast<const float4*>(&xb[(wi + lane) * XWPITCH]);
            const float4 a1 = *reinterpret_cast<const float4*>(&xb[(wi + lane + 32) * XWPITCH]);
            const float4 a2 = *reinterpret_cast<const float4*>(&xb[(wi + lane + 64) * XWPITCH]);
            const float4 a3 = *reinterpret_cast<const float4*>(&xb[(wi + lane + 96) * XWPITCH]);
            r0 = fmaf(q4.x, a0.x, fmaf(q4.y, a0.y, fmaf(q4.z, a0.z, fmaf(q4.w, a0.w, r0))));
            r1 = fmaf(q4.x, a1.x, fmaf(q4.y, a1.y, fmaf(q4.z, a1.z, fmaf(q4.w, a1.w, r1))));
            r2 = fmaf(q4.x, a2.x, fmaf(q4.y, a2.y, fmaf(q4.z, a2.z, fmaf(q4.w, a2.w, r2))));
            r3 = fmaf(q4.x, a3.x, fmaf(q4.y, a3.y, fmaf(q4.z, a3.z, fmaf(q4.w, a3.w, r3))));
        }
        __syncthreads();
    }

    // ---- softmax over the 128 slots (invalid slots carry raw=0, matching ref) ----
    {
        const int i = i0 + wi;
        float m = warpMax(fmaxf(fmaxf(r0, r1), fmaxf(r2, r3)));
        const float e0 = __expf(r0 - m), e1 = __expf(r1 - m),
                    e2 = __expf(r2 - m), e3 = __expf(r3 - m);
        const float inv = 1.f / warpSum(e0 + e1 + e2 + e3);
        int j;
        j = i + lane - WHALF;       sattn[wi][lane]      = (j >= 0 && j < N_UTT) ? e0 * inv : 0.f;
        j = i + lane - WHALF + 32;  sattn[wi][lane + 32] = (j >= 0 && j < N_UTT) ? e1 * inv : 0.f;
        j = i + lane - WHALF + 64;  sattn[wi][lane + 64] = (j >= 0 && j < N_UTT) ? e2 * inv : 0.f;
        j = i + lane - WHALF + 96;  sattn[wi][lane + 96] = (j >= 0 && j < N_UTT) ? e3 * inv : 0.f;
    }
    __syncthreads();   // orders xw reads before coefficient writes below

    // ---- build coefficient tables [jj][li] (vector-loadable) ----
    for (int t = tid; t < NW * G; t += 256) {
        const int jj = t >> 3, li = t & 7;
        const int w = jj - li;
        const float c = (w >= 0 && w < WIN) ? sattn[li][w] : 0.f;  // 0 for invalid j too
        csAp[t] = (w >= WHALF) ? c : 0.f;
        csAs[t] = (w < WHALF) ? c : 0.f;
        csB[t]  = (spkw[jj] == spkw[WHALF + li]) ? 0.5f * c : -0.5f * c;
    }
    __syncthreads();

    // ---- aggregation: thread owns feature d, stream union window ----
    const int d = tid;
    float acc[G];
#pragma unroll
    for (int li = 0; li < G; li++) acc[li] = 0.f;

    const int jlo = (i0 < WHALF) ? (WHALF - i0) : 0;
    const int jhi = min(NW, N_UTT - i0 + WHALF);

#define AGG2(AV, BV, T1V, T2V)                                                   \
    do {                                                                         \
        const float4 a0 = *reinterpret_cast<const float4*>(&(AV)[jj * 8]);       \
        const float4 a1 = *reinterpret_cast<const float4*>(&(AV)[jj * 8 + 4]);   \
        const float4 b0 = *reinterpret_cast<const float4*>(&(BV)[jj * 8]);       \
        const float4 b1 = *reinterpret_cast<const float4*>(&(BV)[jj * 8 + 4]);   \
        acc[0] = fmaf(a0.x, (T1V), fmaf(b0.x, (T2V), acc[0]));                   \
        acc[1] = fmaf(a0.y, (T1V), fmaf(b0.y, (T2V), acc[1]));                   \
        acc[2] = fmaf(a0.z, (T1V), fmaf(b0.z, (T2V), acc[2]));                   \
        acc[3] = fmaf(a0.w, (T1V), fmaf(b0.w, (T2V), acc[3]));                   \
        acc[4] = fmaf(a1.x, (T1V), fmaf(b1.x, (T2V), acc[4]));                   \
        acc[5] = fmaf(a1.y, (T1V), fmaf(b1.y, (T2V), acc[5]));                   \
        acc[6] = fmaf(a1.z, (T1V), fmaf(b1.z, (T2V), acc[6]));                   \
        acc[7] = fmaf(a1.w, (T1V), fmaf(b1.w, (T2V), acc[7]));                   \
    } while (0)

    // region 1: all suc (w < 64 for every li)
    for (int jj = jlo; jj < WHALF; jj++) {
        const size_t off = (size_t)(i0 + jj - WHALF) * DIM + d;
        const float t1 = T1s[off], t2 = T2[off];
        AGG2(csAs, csB, t1, t2);
    }
    // region 2: mixed (j always valid), both direction tables
#pragma unroll
    for (int jj = WHALF; jj < WHALF + G - 1; jj++) {
        const size_t off = (size_t)(i0 + jj - WHALF) * DIM + d;
        const float t1p = T1p[off], t1s = T1s[off], t2 = T2[off];
        const float4 p0 = *reinterpret_cast<const float4*>(&csAp[jj * 8]);
        const float4 p1 = *reinterpret_cast<const float4*>(&csAp[jj * 8 + 4]);
        const float4 s0 = *reinterpret_cast<const float4*>(&csAs[jj * 8]);
        const float4 s1 = *reinterpret_cast<const float4*>(&csAs[jj * 8 + 4]);
        const float4 b0 = *reinterpret_cast<const float4*>(&csB[jj * 8]);
        const float4 b1 = *reinterpret_cast<const float4*>(&csB[jj * 8 + 4]);
        acc[0] = fmaf(p0.x, t1p, fmaf(s0.x, t1s, fmaf(b0.x, t2, acc[0])));
        acc[1] = fmaf(p0.y, t1p, fmaf(s0.y, t1s, fmaf(b0.y, t2, acc[1])));
        acc[2] = fmaf(p0.z, t1p, fmaf(s0.z, t1s, fmaf(b0.z, t2, acc[2])));
        acc[3] = fmaf(p0.w, t1p, fmaf(s0.w, t1s, fmaf(b0.w, t2, acc[3])));
        acc[4] = fmaf(p1.x, t1p, fmaf(s1.x, t1s, fmaf(b1.x, t2, acc[4])));
        acc[5] = fmaf(p1.y, t1p, fmaf(s1.y, t1s, fmaf(b1.y, t2, acc[5])));
        acc[6] = fmaf(p1.z, t1p, fmaf(s1.z, t1s, fmaf(b1.z, t2, acc[6])));
        acc[7] = fmaf(p1.w, t1p, fmaf(s1.w, t1s, fmaf(b1.w, t2, acc[7])));
    }
    // region 3: all pred (w >= 64 for every li)
    for (int jj = WHALF + G - 1; jj < jhi; jj++) {
        const size_t off = (size_t)(i0 + jj - WHALF) * DIM + d;
        const float t1 = T1p[off], t2 = T2[off];
        AGG2(csAp, csB, t1, t2);
    }

    // ---- log_softmax over D: transposed reduction (2 syncs total) ----
    float* const s_acc = &sq[0][0];   // reuse 8 KB (sq dead)
    __syncthreads();                  // everyone past sq/coef reads
#pragma unroll
    for (int li = 0; li < G; li++) s_acc[li * DIM + d] = acc[li];
    __syncthreads();
    {
        // warp wi reduces row wi (256 values, 8 per lane)
        float v[8];
#pragma unroll
        for (int k = 0; k < 8; k++) v[k] = s_acc[wi * DIM + lane + 32 * k];
        float m = v[0];
#pragma unroll
        for (int k = 1; k < 8; k++) m = fmaxf(m, v[k]);
        m = warpMax(m);
        float s = 0.f;
#pragma unroll
        for (int k = 0; k < 8; k++) s += __expf(v[k] - m);
        s = warpSum(s);
        if (lane == 0) slse[wi] = m + logf(s);
    }
    __syncthreads();
#pragma unroll
    for (int li = 0; li < G; li++)
        out[(size_t)(i0 + li) * DIM + d] = acc[li] - slse[li];
}

// ---------------------------------------------------------------------------
extern "C" void kernel_launch(void* const* d_in, const int* in_sizes, int n_in,
                              void* d_out, int out_size) {
    const float* x   = (const float*)d_in[0];
    const int*   spk = (const int*)d_in[1];
    const float* Wa  = (const float*)d_in[2];  // W_att
    const float* Wp  = (const float*)d_in[3];  // W_pred
    const float* Ws  = (const float*)d_in[4];  // W_suc
    const float* Wm  = (const float*)d_in[5];  // W_same
    const float* Wd  = (const float*)d_in[6];  // W_diff
    float* out = (float*)d_out;

    combine_kernel<<<DIM * DIM / 4 / 256, 256>>>(Wp, Ws, Wm, Wd);

    // g_wc device-symbol address: take it via a static device-pointer trick
    static float* wc_base = nullptr;
    if (!wc_base) cudaGetSymbolAddress((void**)&wc_base, g_wc);

    WPtrs wp;
    wp.w[0] = Wa;
    wp.w[1] = wc_base;                  // Wc1 -> T1p
    wp.w[2] = wc_base + DIM * DIM;      // Wc2 -> T1s
    wp.w[3] = wc_base + 2 * DIM * DIM;  // Wc3 -> T2

    dim3 ggrid(N_UTT / 128, 8);
    gemm_kernel<<<ggrid, 256>>>(x, wp);
    fused_kernel<<<N_UTT / G, 256>>>(x, spk, out);
}

// round 10
// speedup vs baseline: 2.4043x; 1.3853x over previous
#include <cuda_runtime.h>
#include <cuda_bf16.h>
#include <cstdint>

#define N_UTT 16384
#define DIM   256
#define WHALF 64
#define WIN   128
#define G     8
#define NW    135
#define DCH   32
#define XWPITCH 36

// Scratch: [0]=Q=x@W_att, [1]=T1p=x@Wc1, [2]=T1s=x@Wc2, [3]=T2=x@Wc3
__device__ float g_scratch[4ULL * N_UTT * DIM];
// bf16 split of x (hi + lo)
__device__ __align__(16) unsigned short g_xhi[N_UTT * DIM];
__device__ __align__(16) unsigned short g_xlo[N_UTT * DIM];
// combined+transposed weights, bf16 split: [widx][n][k]
__device__ __align__(16) unsigned short g_wthi[4 * DIM * DIM];
__device__ __align__(16) unsigned short g_wtlo[4 * DIM * DIM];

__device__ __forceinline__ uint32_t smem_to_u32(const void* p) {
    uint32_t a;
    asm("{ .reg .u64 t; cvta.to.shared.u64 t, %1; cvt.u32.u64 %0, t; }" : "=r"(a) : "l"(p));
    return a;
}
__device__ __forceinline__ void ldsm_x4(uint32_t* r, uint32_t addr) {
    asm volatile("ldmatrix.sync.aligned.m8n8.x4.shared.b16 {%0,%1,%2,%3}, [%4];"
                 : "=r"(r[0]), "=r"(r[1]), "=r"(r[2]), "=r"(r[3]) : "r"(addr));
}
__device__ __forceinline__ void mma16816(float* c, const uint32_t* a, const uint32_t* b) {
    asm volatile(
        "mma.sync.aligned.m16n8k16.row.col.f32.bf16.bf16.f32 "
        "{%0,%1,%2,%3}, {%4,%5,%6,%7}, {%8,%9}, {%0,%1,%2,%3};"
        : "+f"(c[0]), "+f"(c[1]), "+f"(c[2]), "+f"(c[3])
        : "r"(a[0]), "r"(a[1]), "r"(a[2]), "r"(a[3]), "r"(b[0]), "r"(b[1]));
}

// ===========================================================================
// Prep kernels
// ===========================================================================
__device__ __forceinline__ void bf16_split(float v, unsigned short& hi, unsigned short& lo) {
    __nv_bfloat16 h = __float2bfloat16(v);
    float r = v - __bfloat162float(h);
    hi = __bfloat16_as_ushort(h);
    lo = __bfloat16_as_ushort(__float2bfloat16(r));
}

__global__ void split_x_kernel(const float* __restrict__ x) {
    const int i = (blockIdx.x * 256 + threadIdx.x) * 4;
    float4 v = *reinterpret_cast<const float4*>(x + i);
    ushort4 h, l;
    bf16_split(v.x, h.x, l.x);
    bf16_split(v.y, h.y, l.y);
    bf16_split(v.z, h.z, l.z);
    bf16_split(v.w, h.w, l.w);
    *reinterpret_cast<ushort4*>(g_xhi + i) = h;
    *reinterpret_cast<ushort4*>(g_xlo + i) = l;
}

__global__ void prep_w_kernel(const float* __restrict__ Wa, const float* __restrict__ Wp,
                              const float* __restrict__ Ws, const float* __restrict__ Wm,
                              const float* __restrict__ Wd) {
    const int idx = blockIdx.x * 256 + threadIdx.x;   // idx = k*256 + n
    const int k = idx >> 8, n = idx & 255;
    const float p = Wp[idx], s = Ws[idx], m = Wm[idx], d = Wd[idx], a = Wa[idx];
    const float avg = 0.5f * (m + d);
    float vals[4] = {a, p + avg, s + avg, m - d};
    const int tr = n * DIM + k;
#pragma unroll
    for (int w = 0; w < 4; w++) {
        unsigned short hi, lo;
        bf16_split(vals[w], hi, lo);
        g_wthi[w * DIM * DIM + tr] = hi;
        g_wtlo[w * DIM * DIM + tr] = lo;
    }
}

// ===========================================================================
// Warp-MMA bf16x3 GEMM: g_scratch[widx] = X @ W[widx]
// CTA tile 128x128, 8 warps (warp tile 64x32), K chunks of 64.
// smem: padded rows, stride 72 bf16 (144B) -> conflict-free ldmatrix.
// ===========================================================================
#define KC     64
#define SSTR   72                        // bf16 elements per smem row
#define TILEB  (128 * SSTR * 2)          // 18432 bytes per tile
#define SM_AHI 0
#define SM_ALO (TILEB)
#define SM_BHI (2 * TILEB)
#define SM_BLO (3 * TILEB)
#define SM_TOTAL (4 * TILEB)             // 73728 bytes

__global__ void __launch_bounds__(256) gemm_tc_kernel() {
    extern __shared__ __align__(16) char smem[];
    const uint32_t sb = smem_to_u32(smem);
    const int tid  = threadIdx.x;
    const int wid  = tid >> 5;
    const int lane = tid & 31;

    const int row0  = blockIdx.x * 128;
    const int widx  = blockIdx.y >> 1;
    const int ncol0 = (blockIdx.y & 1) * 128;

    float* __restrict__ Cout = g_scratch + (size_t)widx * N_UTT * DIM;
    const unsigned short* __restrict__ wth = g_wthi + widx * DIM * DIM;
    const unsigned short* __restrict__ wtl = g_wtlo + widx * DIM * DIM;

    // warp layout: 2 m-blocks x 4 n-blocks
    const int m0w = (wid & 1) * 64;
    const int n0w = (wid >> 1) * 32;

    float acc[4][4][4];
#pragma unroll
    for (int a = 0; a < 4; a++)
#pragma unroll
        for (int b = 0; b < 4; b++)
#pragma unroll
            for (int c = 0; c < 4; c++) acc[a][b][c] = 0.f;

    // ldmatrix lane base addresses (byte offsets into each tile)
    // A (row-major m16k16 tiles): row = m0 + (lane&15), coloff = (lane>>4)*8
    const uint32_t a_lane_off = (uint32_t)(((m0w + (lane & 15)) * SSTR + ((lane >> 4) << 3)) * 2);
    // B ([n][k], n16k16 tiles): nrow = n0 + (lane&7) + ((lane>>4)<<3), kcol = (lane&8)
    const uint32_t b_lane_off = (uint32_t)(((n0w + (lane & 7) + ((lane >> 4) << 3)) * SSTR + (lane & 8)) * 2);

    for (int c = 0; c < 4; c++) {
        const int k0 = c * KC;
        __syncthreads();   // protect smem from previous chunk's readers
        // stage A hi/lo: rows row0..+127, cols k0..k0+63
#pragma unroll
        for (int s = tid; s < 1024; s += 256) {
            const int r = s >> 3, f = s & 7;
            const uint32_t dst = (uint32_t)((r * SSTR + f * 8) * 2);
            const size_t src = (size_t)(row0 + r) * DIM + k0 + f * 8;
            *reinterpret_cast<uint4*>(smem + SM_AHI + dst) = *reinterpret_cast<const uint4*>(g_xhi + src);
            *reinterpret_cast<uint4*>(smem + SM_ALO + dst) = *reinterpret_cast<const uint4*>(g_xlo + src);
        }
        // stage B hi/lo: n rows ncol0..+127, cols k0..k0+63
#pragma unroll
        for (int s = tid; s < 1024; s += 256) {
            const int n = s >> 3, f = s & 7;
            const uint32_t dst = (uint32_t)((n * SSTR + f * 8) * 2);
            const size_t src = (size_t)(ncol0 + n) * DIM + k0 + f * 8;
            *reinterpret_cast<uint4*>(smem + SM_BHI + dst) = *reinterpret_cast<const uint4*>(wth + src);
            *reinterpret_cast<uint4*>(smem + SM_BLO + dst) = *reinterpret_cast<const uint4*>(wtl + src);
        }
        __syncthreads();

#pragma unroll
        for (int kk = 0; kk < KC; kk += 16) {
            const uint32_t kb = (uint32_t)(kk * 2);
            uint32_t ah[4][4], al[4][4], bh[2][4], bl[2][4];
#pragma unroll
            for (int mt = 0; mt < 4; mt++)
                ldsm_x4(ah[mt], sb + SM_AHI + a_lane_off + (uint32_t)(mt * 16 * SSTR * 2) + kb);
#pragma unroll
            for (int nt = 0; nt < 2; nt++)
                ldsm_x4(bh[nt], sb + SM_BHI + b_lane_off + (uint32_t)(nt * 16 * SSTR * 2) + kb);
            // pass hi*hi
#pragma unroll
            for (int mt = 0; mt < 4; mt++)
#pragma unroll
                for (int n8 = 0; n8 < 4; n8++)
                    mma16816(acc[mt][n8], ah[mt], &bh[n8 >> 1][(n8 & 1) * 2]);
            // pass hi*lo
#pragma unroll
            for (int nt = 0; nt < 2; nt++)
                ldsm_x4(bl[nt], sb + SM_BLO + b_lane_off + (uint32_t)(nt * 16 * SSTR * 2) + kb);
#pragma unroll
            for (int mt = 0; mt < 4; mt++)
#pragma unroll
                for (int n8 = 0; n8 < 4; n8++)
                    mma16816(acc[mt][n8], ah[mt], &bl[n8 >> 1][(n8 & 1) * 2]);
            // pass lo*hi
#pragma unroll
            for (int mt = 0; mt < 4; mt++)
                ldsm_x4(al[mt], sb + SM_ALO + a_lane_off + (uint32_t)(mt * 16 * SSTR * 2) + kb);
#pragma unroll
            for (int mt = 0; mt < 4; mt++)
#pragma unroll
                for (int n8 = 0; n8 < 4; n8++)
                    mma16816(acc[mt][n8], al[mt], &bh[n8 >> 1][(n8 & 1) * 2]);
        }
    }

    // epilogue: C fragment -> global (float2 per reg pair)
    const int qr = lane >> 2, qc = (lane & 3) * 2;
#pragma unroll
    for (int mt = 0; mt < 4; mt++) {
        const int row = row0 + m0w + mt * 16 + qr;
#pragma unroll
        for (int n8 = 0; n8 < 4; n8++) {
            const int col = ncol0 + n0w + n8 * 8 + qc;
            *reinterpret_cast<float2*>(&Cout[(size_t)row * DIM + col]) =
                make_float2(acc[mt][n8][0], acc[mt][n8][1]);
            *reinterpret_cast<float2*>(&Cout[(size_t)(row + 8) * DIM + col]) =
                make_float2(acc[mt][n8][2], acc[mt][n8][3]);
        }
    }
}

// ===========================================================================
// Fused: band attention softmax + relation aggregation + log_softmax
// ===========================================================================
__device__ __forceinline__ float warpMax(float v) {
#pragma unroll
    for (int o = 16; o > 0; o >>= 1) v = fmaxf(v, __shfl_xor_sync(0xffffffffu, v, o));
    return v;
}
__device__ __forceinline__ float warpSum(float v) {
#pragma unroll
    for (int o = 16; o > 0; o >>= 1) v += __shfl_xor_sync(0xffffffffu, v, o);
    return v;
}

__global__ __launch_bounds__(256) void fused_kernel(const float* __restrict__ x,
                                                    const int* __restrict__ spk,
                                                    float* __restrict__ out) {
    __shared__ float  sq[G][DIM];
    __shared__ float4 sbuf4[(NW * XWPITCH + 3) / 4];
    __shared__ float  sattn[G][WIN];
    __shared__ int    spkw[NW];
    __shared__ float  slse[G];

    float* const xw   = reinterpret_cast<float*>(sbuf4);
    float* const csAp = reinterpret_cast<float*>(sbuf4);
    float* const csAs = reinterpret_cast<float*>(sbuf4) + NW * G;
    float* const csB  = reinterpret_cast<float*>(sbuf4) + 2 * NW * G;

    const int i0   = blockIdx.x * G;
    const int tid  = threadIdx.x;
    const int wi   = tid >> 5;
    const int lane = tid & 31;

    const float* __restrict__ Q   = g_scratch;
    const float* __restrict__ T1p = g_scratch + 1ULL * N_UTT * DIM;
    const float* __restrict__ T1s = g_scratch + 2ULL * N_UTT * DIM;
    const float* __restrict__ T2  = g_scratch + 3ULL * N_UTT * DIM;

#pragma unroll
    for (int li = 0; li < G; li++)
        sq[li][tid] = Q[(size_t)(i0 + li) * DIM + tid];
    if (tid < NW) {
        int j = i0 + tid - WHALF;
        j = min(max(j, 0), N_UTT - 1);
        spkw[tid] = spk[j];
    }
    __syncthreads();

    float r0 = 0.f, r1 = 0.f, r2 = 0.f, r3 = 0.f;
    for (int c0 = 0; c0 < DIM; c0 += DCH) {
        for (int t = tid; t < NW * 8; t += 256) {
            const int row = t >> 3, f = t & 7;
            const int j = i0 + row - WHALF;
            float4 v = make_float4(0.f, 0.f, 0.f, 0.f);
            if (j >= 0 && j < N_UTT)
                v = *reinterpret_cast<const float4*>(&x[(size_t)j * DIM + c0 + 4 * f]);
            *reinterpret_cast<float4*>(&xw[row * XWPITCH + 4 * f]) = v;
        }
        __syncthreads();
#pragma unroll
        for (int d4 = 0; d4 < DCH / 4; d4++) {
            const float4 q4 = *reinterpret_cast<const float4*>(&sq[wi][c0 + 4 * d4]);
            const float* xb = &xw[4 * d4];
            const float4 a0 = *reinterpret_cast<const float4*>(&xb[(wi + lane) * XWPITCH]);
            const float4 a1 = *reinterpret_cast<const float4*>(&xb[(wi + lane + 32) * XWPITCH]);
            const float4 a2 = *reinterpret_cast<const float4*>(&xb[(wi + lane + 64) * XWPITCH]);
            const float4 a3 = *reinterpret_cast<const float4*>(&xb[(wi + lane + 96) * XWPITCH]);
            r0 = fmaf(q4.x, a0.x, fmaf(q4.y, a0.y, fmaf(q4.z, a0.z, fmaf(q4.w, a0.w, r0))));
            r1 = fmaf(q4.x, a1.x, fmaf(q4.y, a1.y, fmaf(q4.z, a1.z, fmaf(q4.w, a1.w, r1))));
            r2 = fmaf(q4.x, a2.x, fmaf(q4.y, a2.y, fmaf(q4.z, a2.z, fmaf(q4.w, a2.w, r2))));
            r3 = fmaf(q4.x, a3.x, fmaf(q4.y, a3.y, fmaf(q4.z, a3.z, fmaf(q4.w, a3.w, r3))));
        }
        __syncthreads();
    }

    {
        const int i = i0 + wi;
        float m = warpMax(fmaxf(fmaxf(r0, r1), fmaxf(r2, r3)));
        const float e0 = __expf(r0 - m), e1 = __expf(r1 - m),
                    e2 = __expf(r2 - m), e3 = __expf(r3 - m);
        const float inv = 1.f / warpSum(e0 + e1 + e2 + e3);
        int j;
        j = i + lane - WHALF;       sattn[wi][lane]      = (j >= 0 && j < N_UTT) ? e0 * inv : 0.f;
        j = i + lane - WHALF + 32;  sattn[wi][lane + 32] = (j >= 0 && j < N_UTT) ? e1 * inv : 0.f;
        j = i + lane - WHALF + 64;  sattn[wi][lane + 64] = (j >= 0 && j < N_UTT) ? e2 * inv : 0.f;
        j = i + lane - WHALF + 96;  sattn[wi][lane + 96] = (j >= 0 && j < N_UTT) ? e3 * inv : 0.f;
    }
    __syncthreads();

    for (int t = tid; t < NW * G; t += 256) {
        const int jj = t >> 3, li = t & 7;
        const int w = jj - li;
        const float c = (w >= 0 && w < WIN) ? sattn[li][w] : 0.f;
        csAp[t] = (w >= WHALF) ? c : 0.f;
        csAs[t] = (w < WHALF) ? c : 0.f;
        csB[t]  = (spkw[jj] == spkw[WHALF + li]) ? 0.5f * c : -0.5f * c;
    }
    __syncthreads();

    const int d = tid;
    float acc[G];
#pragma unroll
    for (int li = 0; li < G; li++) acc[li] = 0.f;

    const int jlo = (i0 < WHALF) ? (WHALF - i0) : 0;
    const int jhi = min(NW, N_UTT - i0 + WHALF);

#define AGG2(AV, BV, T1V, T2V)                                                   \
    do {                                                                         \
        const float4 a0 = *reinterpret_cast<const float4*>(&(AV)[jj * 8]);       \
        const float4 a1 = *reinterpret_cast<const float4*>(&(AV)[jj * 8 + 4]);   \
        const float4 b0 = *reinterpret_cast<const float4*>(&(BV)[jj * 8]);       \
        const float4 b1 = *reinterpret_cast<const float4*>(&(BV)[jj * 8 + 4]);   \
        acc[0] = fmaf(a0.x, (T1V), fmaf(b0.x, (T2V), acc[0]));                   \
        acc[1] = fmaf(a0.y, (T1V), fmaf(b0.y, (T2V), acc[1]));                   \
        acc[2] = fmaf(a0.z, (T1V), fmaf(b0.z, (T2V), acc[2]));                   \
        acc[3] = fmaf(a0.w, (T1V), fmaf(b0.w, (T2V), acc[3]));                   \
        acc[4] = fmaf(a1.x, (T1V), fmaf(b1.x, (T2V), acc[4]));                   \
        acc[5] = fmaf(a1.y, (T1V), fmaf(b1.y, (T2V), acc[5]));                   \
        acc[6] = fmaf(a1.z, (T1V), fmaf(b1.z, (T2V), acc[6]));                   \
        acc[7] = fmaf(a1.w, (T1V), fmaf(b1.w, (T2V), acc[7]));                   \
    } while (0)

    for (int jj = jlo; jj < WHALF; jj++) {
        const size_t off = (size_t)(i0 + jj - WHALF) * DIM + d;
        const float t1 = T1s[off], t2 = T2[off];
        AGG2(csAs, csB, t1, t2);
    }
#pragma unroll
    for (int jj = WHALF; jj < WHALF + G - 1; jj++) {
        const size_t off = (size_t)(i0 + jj - WHALF) * DIM + d;
        const float t1p = T1p[off], t1s = T1s[off], t2 = T2[off];
        const float4 p0 = *reinterpret_cast<const float4*>(&csAp[jj * 8]);
        const float4 p1 = *reinterpret_cast<const float4*>(&csAp[jj * 8 + 4]);
        const float4 s0 = *reinterpret_cast<const float4*>(&csAs[jj * 8]);
        const float4 s1 = *reinterpret_cast<const float4*>(&csAs[jj * 8 + 4]);
        const float4 b0 = *reinterpret_cast<const float4*>(&csB[jj * 8]);
        const float4 b1 = *reinterpret_cast<const float4*>(&csB[jj * 8 + 4]);
        acc[0] = fmaf(p0.x, t1p, fmaf(s0.x, t1s, fmaf(b0.x, t2, acc[0])));
        acc[1] = fmaf(p0.y, t1p, fmaf(s0.y, t1s, fmaf(b0.y, t2, acc[1])));
        acc[2] = fmaf(p0.z, t1p, fmaf(s0.z, t1s, fmaf(b0.z, t2, acc[2])));
        acc[3] = fmaf(p0.w, t1p, fmaf(s0.w, t1s, fmaf(b0.w, t2, acc[3])));
        acc[4] = fmaf(p1.x, t1p, fmaf(s1.x, t1s, fmaf(b1.x, t2, acc[4])));
        acc[5] = fmaf(p1.y, t1p, fmaf(s1.y, t1s, fmaf(b1.y, t2, acc[5])));
        acc[6] = fmaf(p1.z, t1p, fmaf(s1.z, t1s, fmaf(b1.z, t2, acc[6])));
        acc[7] = fmaf(p1.w, t1p, fmaf(s1.w, t1s, fmaf(b1.w, t2, acc[7])));
    }
    for (int jj = WHALF + G - 1; jj < jhi; jj++) {
        const size_t off = (size_t)(i0 + jj - WHALF) * DIM + d;
        const float t1 = T1p[off], t2 = T2[off];
        AGG2(csAp, csB, t1, t2);
    }

    float* const s_acc = &sq[0][0];
    __syncthreads();
#pragma unroll
    for (int li = 0; li < G; li++) s_acc[li * DIM + d] = acc[li];
    __syncthreads();
    {
        float v[8];
#pragma unroll
        for (int k = 0; k < 8; k++) v[k] = s_acc[wi * DIM + lane + 32 * k];
        float m = v[0];
#pragma unroll
        for (int k = 1; k < 8; k++) m = fmaxf(m, v[k]);
        m = warpMax(m);
        float s = 0.f;
#pragma unroll
        for (int k = 0; k < 8; k++) s += __expf(v[k] - m);
        s = warpSum(s);
        if (lane == 0) slse[wi] = m + logf(s);
    }
    __syncthreads();
#pragma unroll
    for (int li = 0; li < G; li++)
        out[(size_t)(i0 + li) * DIM + d] = acc[li] - slse[li];
}

// ---------------------------------------------------------------------------
extern "C" void kernel_launch(void* const* d_in, const int* in_sizes, int n_in,
                              void* d_out, int out_size) {
    const float* x   = (const float*)d_in[0];
    const int*   spk = (const int*)d_in[1];
    const float* Wa  = (const float*)d_in[2];
    const float* Wp  = (const float*)d_in[3];
    const float* Ws  = (const float*)d_in[4];
    const float* Wm  = (const float*)d_in[5];
    const float* Wd  = (const float*)d_in[6];
    float* out = (float*)d_out;

    cudaFuncSetAttribute(gemm_tc_kernel, cudaFuncAttributeMaxDynamicSharedMemorySize, SM_TOTAL);

    split_x_kernel<<<N_UTT * DIM / 1024, 256>>>(x);
    prep_w_kernel<<<DIM * DIM / 256, 256>>>(Wa, Wp, Ws, Wm, Wd);
    gemm_tc_kernel<<<dim3(N_UTT / 128, 8), 256, SM_TOTAL>>>();
    fused_kernel<<<N_UTT / G, 256>>>(x, spk, out);
}

// round 11
// speedup vs baseline: 2.6570x; 1.1051x over previous
#include <cuda_runtime.h>
#include <cuda_bf16.h>
#include <cstdint>

#define N_UTT 16384
#define DIM   256
#define WHALF 64
#define WIN   128
#define G     8
#define NW    135

// Scratch: [0]=Q=x@W_att, [1]=T1p=x@Wc1, [2]=T1s=x@Wc2, [3]=T2=x@Wc3
__device__ float g_scratch[4ULL * N_UTT * DIM];
__device__ __align__(16) unsigned short g_xhi[N_UTT * DIM];
__device__ __align__(16) unsigned short g_xlo[N_UTT * DIM];
__device__ __align__(16) unsigned short g_wthi[4 * DIM * DIM];
__device__ __align__(16) unsigned short g_wtlo[4 * DIM * DIM];

__device__ __forceinline__ uint32_t smem_to_u32(const void* p) {
    uint32_t a;
    asm("{ .reg .u64 t; cvta.to.shared.u64 t, %1; cvt.u32.u64 %0, t; }" : "=r"(a) : "l"(p));
    return a;
}
__device__ __forceinline__ void ldsm_x4(uint32_t* r, uint32_t addr) {
    asm volatile("ldmatrix.sync.aligned.m8n8.x4.shared.b16 {%0,%1,%2,%3}, [%4];"
                 : "=r"(r[0]), "=r"(r[1]), "=r"(r[2]), "=r"(r[3]) : "r"(addr));
}
__device__ __forceinline__ void ldsm_x2(uint32_t* r, uint32_t addr) {
    asm volatile("ldmatrix.sync.aligned.m8n8.x2.shared.b16 {%0,%1}, [%2];"
                 : "=r"(r[0]), "=r"(r[1]) : "r"(addr));
}
__device__ __forceinline__ void mma16816(float* c, const uint32_t* a, const uint32_t* b) {
    asm volatile(
        "mma.sync.aligned.m16n8k16.row.col.f32.bf16.bf16.f32 "
        "{%0,%1,%2,%3}, {%4,%5,%6,%7}, {%8,%9}, {%0,%1,%2,%3};"
        : "+f"(c[0]), "+f"(c[1]), "+f"(c[2]), "+f"(c[3])
        : "r"(a[0]), "r"(a[1]), "r"(a[2]), "r"(a[3]), "r"(b[0]), "r"(b[1]));
}

// ===========================================================================
// Prep kernels
// ===========================================================================
__device__ __forceinline__ void bf16_split(float v, unsigned short& hi, unsigned short& lo) {
    __nv_bfloat16 h = __float2bfloat16(v);
    float r = v - __bfloat162float(h);
    hi = __bfloat16_as_ushort(h);
    lo = __bfloat16_as_ushort(__float2bfloat16(r));
}

__global__ void split_x_kernel(const float* __restrict__ x) {
    const int i = (blockIdx.x * 256 + threadIdx.x) * 4;
    float4 v = *reinterpret_cast<const float4*>(x + i);
    ushort4 h, l;
    bf16_split(v.x, h.x, l.x);
    bf16_split(v.y, h.y, l.y);
    bf16_split(v.z, h.z, l.z);
    bf16_split(v.w, h.w, l.w);
    *reinterpret_cast<ushort4*>(g_xhi + i) = h;
    *reinterpret_cast<ushort4*>(g_xlo + i) = l;
}

__global__ void prep_w_kernel(const float* __restrict__ Wa, const float* __restrict__ Wp,
                              const float* __restrict__ Ws, const float* __restrict__ Wm,
                              const float* __restrict__ Wd) {
    const int idx = blockIdx.x * 256 + threadIdx.x;   // idx = k*256 + n
    const int k = idx >> 8, n = idx & 255;
    const float p = Wp[idx], s = Ws[idx], m = Wm[idx], d = Wd[idx], a = Wa[idx];
    const float avg = 0.5f * (m + d);
    float vals[4] = {a, p + avg, s + avg, m - d};
    const int tr = n * DIM + k;
#pragma unroll
    for (int w = 0; w < 4; w++) {
        unsigned short hi, lo;
        bf16_split(vals[w], hi, lo);
        g_wthi[w * DIM * DIM + tr] = hi;
        g_wtlo[w * DIM * DIM + tr] = lo;
    }
}

// ===========================================================================
// Warp-MMA bf16x3 GEMM (unchanged from passing R10)
// ===========================================================================
#define KC     64
#define SSTR   72
#define TILEB  (128 * SSTR * 2)
#define SM_AHI 0
#define SM_ALO (TILEB)
#define SM_BHI (2 * TILEB)
#define SM_BLO (3 * TILEB)
#define SM_TOTAL (4 * TILEB)

__global__ void __launch_bounds__(256) gemm_tc_kernel() {
    extern __shared__ __align__(16) char smem[];
    const uint32_t sb = smem_to_u32(smem);
    const int tid  = threadIdx.x;
    const int wid  = tid >> 5;
    const int lane = tid & 31;

    const int row0  = blockIdx.x * 128;
    const int widx  = blockIdx.y >> 1;
    const int ncol0 = (blockIdx.y & 1) * 128;

    float* __restrict__ Cout = g_scratch + (size_t)widx * N_UTT * DIM;
    const unsigned short* __restrict__ wth = g_wthi + widx * DIM * DIM;
    const unsigned short* __restrict__ wtl = g_wtlo + widx * DIM * DIM;

    const int m0w = (wid & 1) * 64;
    const int n0w = (wid >> 1) * 32;

    float acc[4][4][4];
#pragma unroll
    for (int a = 0; a < 4; a++)
#pragma unroll
        for (int b = 0; b < 4; b++)
#pragma unroll
            for (int c = 0; c < 4; c++) acc[a][b][c] = 0.f;

    const uint32_t a_lane_off = (uint32_t)(((m0w + (lane & 15)) * SSTR + ((lane >> 4) << 3)) * 2);
    const uint32_t b_lane_off = (uint32_t)(((n0w + (lane & 7) + ((lane >> 4) << 3)) * SSTR + (lane & 8)) * 2);

    for (int c = 0; c < 4; c++) {
        const int k0 = c * KC;
        __syncthreads();
#pragma unroll
        for (int s = tid; s < 1024; s += 256) {
            const int r = s >> 3, f = s & 7;
            const uint32_t dst = (uint32_t)((r * SSTR + f * 8) * 2);
            const size_t src = (size_t)(row0 + r) * DIM + k0 + f * 8;
            *reinterpret_cast<uint4*>(smem + SM_AHI + dst) = *reinterpret_cast<const uint4*>(g_xhi + src);
            *reinterpret_cast<uint4*>(smem + SM_ALO + dst) = *reinterpret_cast<const uint4*>(g_xlo + src);
        }
#pragma unroll
        for (int s = tid; s < 1024; s += 256) {
            const int n = s >> 3, f = s & 7;
            const uint32_t dst = (uint32_t)((n * SSTR + f * 8) * 2);
            const size_t src = (size_t)(ncol0 + n) * DIM + k0 + f * 8;
            *reinterpret_cast<uint4*>(smem + SM_BHI + dst) = *reinterpret_cast<const uint4*>(wth + src);
            *reinterpret_cast<uint4*>(smem + SM_BLO + dst) = *reinterpret_cast<const uint4*>(wtl + src);
        }
        __syncthreads();

#pragma unroll
        for (int kk = 0; kk < KC; kk += 16) {
            const uint32_t kb = (uint32_t)(kk * 2);
            uint32_t ah[4][4], al[4][4], bh[2][4], bl[2][4];
#pragma unroll
            for (int mt = 0; mt < 4; mt++)
                ldsm_x4(ah[mt], sb + SM_AHI + a_lane_off + (uint32_t)(mt * 16 * SSTR * 2) + kb);
#pragma unroll
            for (int nt = 0; nt < 2; nt++)
                ldsm_x4(bh[nt], sb + SM_BHI + b_lane_off + (uint32_t)(nt * 16 * SSTR * 2) + kb);
#pragma unroll
            for (int mt = 0; mt < 4; mt++)
#pragma unroll
                for (int n8 = 0; n8 < 4; n8++)
                    mma16816(acc[mt][n8], ah[mt], &bh[n8 >> 1][(n8 & 1) * 2]);
#pragma unroll
            for (int nt = 0; nt < 2; nt++)
                ldsm_x4(bl[nt], sb + SM_BLO + b_lane_off + (uint32_t)(nt * 16 * SSTR * 2) + kb);
#pragma unroll
            for (int mt = 0; mt < 4; mt++)
#pragma unroll
                for (int n8 = 0; n8 < 4; n8++)
                    mma16816(acc[mt][n8], ah[mt], &bl[n8 >> 1][(n8 & 1) * 2]);
#pragma unroll
            for (int mt = 0; mt < 4; mt++)
                ldsm_x4(al[mt], sb + SM_ALO + a_lane_off + (uint32_t)(mt * 16 * SSTR * 2) + kb);
#pragma unroll
            for (int mt = 0; mt < 4; mt++)
#pragma unroll
                for (int n8 = 0; n8 < 4; n8++)
                    mma16816(acc[mt][n8], al[mt], &bh[n8 >> 1][(n8 & 1) * 2]);
        }
    }

    const int qr = lane >> 2, qc = (lane & 3) * 2;
#pragma unroll
    for (int mt = 0; mt < 4; mt++) {
        const int row = row0 + m0w + mt * 16 + qr;
#pragma unroll
        for (int n8 = 0; n8 < 4; n8++) {
            const int col = ncol0 + n0w + n8 * 8 + qc;
            *reinterpret_cast<float2*>(&Cout[(size_t)row * DIM + col]) =
                make_float2(acc[mt][n8][0], acc[mt][n8][1]);
            *reinterpret_cast<float2*>(&Cout[(size_t)(row + 8) * DIM + col]) =
                make_float2(acc[mt][n8][2], acc[mt][n8][3]);
        }
    }
}

// ===========================================================================
// Fused: MMA band attention + softmax + relation aggregation + log_softmax
// ===========================================================================
#define KCF    32            // attention K chunk
#define AW_STR 40            // window smem stride (bf16): 20 words -> conflict-free ldsm
#define Q_STR  264           // q smem stride (bf16): 132 words -> conflict-free ldsm
#define NPAD   144           // padded window rows (9 m16 tiles)

// smem byte offsets (phase A)
#define OFF_AWH   0                       // 144*80   = 11520
#define OFF_AWL   11520                   // 11520
#define OFF_QH    23040                   // 8*528    = 4224
#define OFF_QL    27264                   // 4224
#define OFF_SLOG  31488                   // 144*9*4  = 5184
#define OFF_SATTN 36672                   // 8*128*4  = 4096
#define OFF_SPKW  40768                   // 136*4    = 544
#define OFF_SLSE  41312                   // 32
#define SMF_TOTAL 41344
// phase B aliases (over AWH/AWL region, 23040 bytes)
#define OFF_CSAP  0                       // 1080*4 = 4320
#define OFF_CSAS  4320
#define OFF_CSB   8640
#define OFF_SACC  13056                   // 8*256*4 = 8192  (ends 21248 < 23040)

__device__ __forceinline__ float warpMax(float v) {
#pragma unroll
    for (int o = 16; o > 0; o >>= 1) v = fmaxf(v, __shfl_xor_sync(0xffffffffu, v, o));
    return v;
}
__device__ __forceinline__ float warpSum(float v) {
#pragma unroll
    for (int o = 16; o > 0; o >>= 1) v += __shfl_xor_sync(0xffffffffu, v, o);
    return v;
}

__global__ __launch_bounds__(256) void fused_kernel(const int* __restrict__ spk,
                                                    float* __restrict__ out) {
    static __shared__ __align__(16) char sm[SMF_TOTAL];
    const uint32_t sb = smem_to_u32(sm);

    const int i0   = blockIdx.x * G;
    const int tid  = threadIdx.x;
    const int wi   = tid >> 5;
    const int lane = tid & 31;

    const float* __restrict__ Q   = g_scratch;
    const float* __restrict__ T1p = g_scratch + 1ULL * N_UTT * DIM;
    const float* __restrict__ T1s = g_scratch + 2ULL * N_UTT * DIM;
    const float* __restrict__ T2  = g_scratch + 3ULL * N_UTT * DIM;

    float* const slog  = reinterpret_cast<float*>(sm + OFF_SLOG);
    float* const sattn = reinterpret_cast<float*>(sm + OFF_SATTN);
    int*   const spkw  = reinterpret_cast<int*>(sm + OFF_SPKW);
    float* const slse  = reinterpret_cast<float*>(sm + OFF_SLSE);

    // ---- load Q rows fp32, split to bf16 hi/lo in smem ----
    {
        const int row = tid >> 5;
        const int c   = (tid & 31) * 8;
        const float* qs = Q + (size_t)(i0 + row) * DIM + c;
        float4 v0 = *reinterpret_cast<const float4*>(qs);
        float4 v1 = *reinterpret_cast<const float4*>(qs + 4);
        unsigned short hh[8], ll[8];
        bf16_split(v0.x, hh[0], ll[0]); bf16_split(v0.y, hh[1], ll[1]);
        bf16_split(v0.z, hh[2], ll[2]); bf16_split(v0.w, hh[3], ll[3]);
        bf16_split(v1.x, hh[4], ll[4]); bf16_split(v1.y, hh[5], ll[5]);
        bf16_split(v1.z, hh[6], ll[6]); bf16_split(v1.w, hh[7], ll[7]);
        *reinterpret_cast<uint4*>(sm + OFF_QH + row * (Q_STR * 2) + c * 2) = *reinterpret_cast<uint4*>(hh);
        *reinterpret_cast<uint4*>(sm + OFF_QL + row * (Q_STR * 2) + c * 2) = *reinterpret_cast<uint4*>(ll);
    }
    if (tid < NW) {
        int j = i0 + tid - WHALF;
        j = min(max(j, 0), N_UTT - 1);
        spkw[tid] = spk[j];
    }

    // ---- band QK^T via m16n8k16 bf16x3 ----
    float facc[2][4];
#pragma unroll
    for (int t = 0; t < 2; t++)
#pragma unroll
        for (int k = 0; k < 4; k++) facc[t][k] = 0.f;

    const uint32_t aoff = (uint32_t)(((lane & 15) * AW_STR + ((lane >> 4) << 3)) * 2);
    const uint32_t boff = (uint32_t)(((lane & 7) * Q_STR + (lane & 8)) * 2);

    for (int c = 0; c < 8; c++) {
        __syncthreads();   // protect window buffer (and Q/spkw writes on c==0)
        // stage window chunk: rows 0..143, cols c*32..+31, bf16 hi/lo, zero-filled
        for (int s = tid; s < 576; s += 256) {
            const int r = s >> 2, f = s & 3;
            const int j = i0 + r - WHALF;
            uint4 vh = make_uint4(0, 0, 0, 0), vl = make_uint4(0, 0, 0, 0);
            if (r < NW && j >= 0 && j < N_UTT) {
                const size_t src = (size_t)j * DIM + c * KCF + f * 8;
                vh = *reinterpret_cast<const uint4*>(g_xhi + src);
                vl = *reinterpret_cast<const uint4*>(g_xlo + src);
            }
            *reinterpret_cast<uint4*>(sm + OFF_AWH + r * (AW_STR * 2) + f * 16) = vh;
            *reinterpret_cast<uint4*>(sm + OFF_AWL + r * (AW_STR * 2) + f * 16) = vl;
        }
        __syncthreads();
#pragma unroll
        for (int ks = 0; ks < 2; ks++) {
            uint32_t bh[2], bl[2];
            ldsm_x2(bh, sb + OFF_QH + boff + (uint32_t)(c * KCF + ks * 16) * 2);
            ldsm_x2(bl, sb + OFF_QL + boff + (uint32_t)(c * KCF + ks * 16) * 2);
            int ti = 0;
            for (int mt = wi; mt < 9; mt += 8, ti++) {
                uint32_t ah[4], al[4];
                const uint32_t mtoff = (uint32_t)(mt * 16 * AW_STR * 2) + (uint32_t)(ks * 32);
                ldsm_x4(ah, sb + OFF_AWH + mtoff + aoff);
                ldsm_x4(al, sb + OFF_AWL + mtoff + aoff);
                mma16816(facc[ti], ah, bh);
                mma16816(facc[ti], ah, bl);
                mma16816(facc[ti], al, bh);
            }
        }
    }
    // fragments -> slog[row][li], stride 9
    {
        const int qr = lane >> 2, qc = (lane & 3) * 2;
        int ti = 0;
        for (int mt = wi; mt < 9; mt += 8, ti++) {
            const int r = mt * 16 + qr;
            slog[r * 9 + qc]           = facc[ti][0];
            slog[r * 9 + qc + 1]       = facc[ti][1];
            slog[(r + 8) * 9 + qc]     = facc[ti][2];
            slog[(r + 8) * 9 + qc + 1] = facc[ti][3];
        }
    }
    __syncthreads();

    // ---- softmax: warp wi owns row i0+wi; logit(li,w) = slog[li+w][li] ----
    {
        const int i = i0 + wi;
        float v0 = slog[(wi + lane) * 9 + wi];
        float v1 = slog[(wi + lane + 32) * 9 + wi];
        float v2 = slog[(wi + lane + 64) * 9 + wi];
        float v3 = slog[(wi + lane + 96) * 9 + wi];
        float m = warpMax(fmaxf(fmaxf(v0, v1), fmaxf(v2, v3)));
        const float e0 = __expf(v0 - m), e1 = __expf(v1 - m),
                    e2 = __expf(v2 - m), e3 = __expf(v3 - m);
        const float inv = 1.f / warpSum(e0 + e1 + e2 + e3);
        int j;
        j = i + lane - WHALF;       sattn[wi * WIN + lane]      = (j >= 0 && j < N_UTT) ? e0 * inv : 0.f;
        j = i + lane - WHALF + 32;  sattn[wi * WIN + lane + 32] = (j >= 0 && j < N_UTT) ? e1 * inv : 0.f;
        j = i + lane - WHALF + 64;  sattn[wi * WIN + lane + 64] = (j >= 0 && j < N_UTT) ? e2 * inv : 0.f;
        j = i + lane - WHALF + 96;  sattn[wi * WIN + lane + 96] = (j >= 0 && j < N_UTT) ? e3 * inv : 0.f;
    }
    __syncthreads();

    // ---- coefficient tables [jj][li] (alias window buffer) ----
    float* const csAp = reinterpret_cast<float*>(sm + OFF_CSAP);
    float* const csAs = reinterpret_cast<float*>(sm + OFF_CSAS);
    float* const csB  = reinterpret_cast<float*>(sm + OFF_CSB);
    for (int t = tid; t < NW * G; t += 256) {
        const int jj = t >> 3, li = t & 7;
        const int w = jj - li;
        const float c = (w >= 0 && w < WIN) ? sattn[li * WIN + w] : 0.f;
        csAp[t] = (w >= WHALF) ? c : 0.f;
        csAs[t] = (w < WHALF) ? c : 0.f;
        csB[t]  = (spkw[jj] == spkw[WHALF + li]) ? 0.5f * c : -0.5f * c;
    }
    __syncthreads();

    // ---- aggregation: thread owns feature d ----
    const int d = tid;
    float acc[G];
#pragma unroll
    for (int li = 0; li < G; li++) acc[li] = 0.f;

    const int jlo = (i0 < WHALF) ? (WHALF - i0) : 0;
    const int jhi = min(NW, N_UTT - i0 + WHALF);

#define AGG2(AV, BV, T1V, T2V)                                                   \
    do {                                                                         \
        const float4 a0 = *reinterpret_cast<const float4*>(&(AV)[jj * 8]);       \
        const float4 a1 = *reinterpret_cast<const float4*>(&(AV)[jj * 8 + 4]);   \
        const float4 b0 = *reinterpret_cast<const float4*>(&(BV)[jj * 8]);       \
        const float4 b1 = *reinterpret_cast<const float4*>(&(BV)[jj * 8 + 4]);   \
        acc[0] = fmaf(a0.x, (T1V), fmaf(b0.x, (T2V), acc[0]));                   \
        acc[1] = fmaf(a0.y, (T1V), fmaf(b0.y, (T2V), acc[1]));                   \
        acc[2] = fmaf(a0.z, (T1V), fmaf(b0.z, (T2V), acc[2]));                   \
        acc[3] = fmaf(a0.w, (T1V), fmaf(b0.w, (T2V), acc[3]));                   \
        acc[4] = fmaf(a1.x, (T1V), fmaf(b1.x, (T2V), acc[4]));                   \
        acc[5] = fmaf(a1.y, (T1V), fmaf(b1.y, (T2V), acc[5]));                   \
        acc[6] = fmaf(a1.z, (T1V), fmaf(b1.z, (T2V), acc[6]));                   \
        acc[7] = fmaf(a1.w, (T1V), fmaf(b1.w, (T2V), acc[7]));                   \
    } while (0)

#pragma unroll 4
    for (int jj = jlo; jj < WHALF; jj++) {
        const size_t off = (size_t)(i0 + jj - WHALF) * DIM + d;
        const float t1 = T1s[off], t2 = T2[off];
        AGG2(csAs, csB, t1, t2);
    }
#pragma unroll
    for (int jj = WHALF; jj < WHALF + G - 1; jj++) {
        const size_t off = (size_t)(i0 + jj - WHALF) * DIM + d;
        const float t1p = T1p[off], t1s = T1s[off], t2 = T2[off];
        const float4 p0 = *reinterpret_cast<const float4*>(&csAp[jj * 8]);
        const float4 p1 = *reinterpret_cast<const float4*>(&csAp[jj * 8 + 4]);
        const float4 s0 = *reinterpret_cast<const float4*>(&csAs[jj * 8]);
        const float4 s1 = *reinterpret_cast<const float4*>(&csAs[jj * 8 + 4]);
        const float4 b0 = *reinterpret_cast<const float4*>(&csB[jj * 8]);
        const float4 b1 = *reinterpret_cast<const float4*>(&csB[jj * 8 + 4]);
        acc[0] = fmaf(p0.x, t1p, fmaf(s0.x, t1s, fmaf(b0.x, t2, acc[0])));
        acc[1] = fmaf(p0.y, t1p, fmaf(s0.y, t1s, fmaf(b0.y, t2, acc[1])));
        acc[2] = fmaf(p0.z, t1p, fmaf(s0.z, t1s, fmaf(b0.z, t2, acc[2])));
        acc[3] = fmaf(p0.w, t1p, fmaf(s0.w, t1s, fmaf(b0.w, t2, acc[3])));
        acc[4] = fmaf(p1.x, t1p, fmaf(s1.x, t1s, fmaf(b1.x, t2, acc[4])));
        acc[5] = fmaf(p1.y, t1p, fmaf(s1.y, t1s, fmaf(b1.y, t2, acc[5])));
        acc[6] = fmaf(p1.z, t1p, fmaf(s1.z, t1s, fmaf(b1.z, t2, acc[6])));
        acc[7] = fmaf(p1.w, t1p, fmaf(s1.w, t1s, fmaf(b1.w, t2, acc[7])));
    }
#pragma unroll 4
    for (int jj = WHALF + G - 1; jj < jhi; jj++) {
        const size_t off = (size_t)(i0 + jj - WHALF) * DIM + d;
        const float t1 = T1p[off], t2 = T2[off];
        AGG2(csAp, csB, t1, t2);
    }

    // ---- log_softmax over D (transposed reduction) ----
    float* const s_acc = reinterpret_cast<float*>(sm + OFF_SACC);
    __syncthreads();
#pragma unroll
    for (int li = 0; li < G; li++) s_acc[li * DIM + d] = acc[li];
    __syncthreads();
    {
        float v[8];
#pragma unroll
        for (int k = 0; k < 8; k++) v[k] = s_acc[wi * DIM + lane + 32 * k];
        float m = v[0];
#pragma unroll
        for (int k = 1; k < 8; k++) m = fmaxf(m, v[k]);
        m = warpMax(m);
        float s = 0.f;
#pragma unroll
        for (int k = 0; k < 8; k++) s += __expf(v[k] - m);
        s = warpSum(s);
        if (lane == 0) slse[wi] = m + logf(s);
    }
    __syncthreads();
#pragma unroll
    for (int li = 0; li < G; li++)
        out[(size_t)(i0 + li) * DIM + d] = acc[li] - slse[li];
}

// ---------------------------------------------------------------------------
extern "C" void kernel_launch(void* const* d_in, const int* in_sizes, int n_in,
                              void* d_out, int out_size) {
    const float* x   = (const float*)d_in[0];
    const int*   spk = (const int*)d_in[1];
    const float* Wa  = (const float*)d_in[2];
    const float* Wp  = (const float*)d_in[3];
    const float* Ws  = (const float*)d_in[4];
    const float* Wm  = (const float*)d_in[5];
    const float* Wd  = (const float*)d_in[6];
    float* out = (float*)d_out;

    cudaFuncSetAttribute(gemm_tc_kernel, cudaFuncAttributeMaxDynamicSharedMemorySize, SM_TOTAL);

    split_x_kernel<<<N_UTT * DIM / 1024, 256>>>(x);
    prep_w_kernel<<<DIM * DIM / 256, 256>>>(Wa, Wp, Ws, Wm, Wd);
    gemm_tc_kernel<<<dim3(N_UTT / 128, 8), 256, SM_TOTAL>>>();
    fused_kernel<<<N_UTT / G, 256>>>(spk, out);
}